// round 2
// baseline (speedup 1.0000x reference)
#include <cuda_runtime.h>
#include <cuda_bf16.h>

#define NCLS 19
#define HW (512 * 512)
#define NBATCH 8
#define BLOCKS_PER_N 128
#define THREADS 256
#define PIX_PER_BLOCK (HW / BLOCKS_PER_N)            // 2048
#define ITERS (PIX_PER_BLOCK / (THREADS * 2))        // 4 (2 pixels/thread/iter)

// Scratch accumulators (allocation-free: __device__ globals)
__device__ float g_inter[NBATCH * NCLS];
__device__ float g_psum [NBATCH * NCLS];
__device__ float g_tsum [NBATCH * NCLS];
__device__ int   g_t64;   // 1 if target is int64, 0 if int32

// ---------------------------------------------------------------------------
// Kernel 0: zero scratch + detect target dtype layout.
// target values are 0..18. If stored little-endian int64, every odd 32-bit
// word is 0. If int32, odd words are random 0..18 (P(all 32 zero) ~ (1/19)^32).
// ---------------------------------------------------------------------------
__global__ void k_init(const unsigned int* __restrict__ tgt_words) {
    int i = threadIdx.x;
    if (i < NBATCH * NCLS) {
        g_inter[i] = 0.0f;
        g_psum[i]  = 0.0f;
        g_tsum[i]  = 0.0f;
    }
    if (i == 0) {
        bool is64 = true;
        #pragma unroll
        for (int j = 1; j < 64; j += 2) is64 &= (tgt_words[j] == 0u);
        g_t64 = is64 ? 1 : 0;
    }
}

// ---------------------------------------------------------------------------
// Kernel 1: main streaming reduction.
// Each block owns a contiguous 2048-pixel chunk of one sample n. Each thread
// handles 2 adjacent pixels per iteration (float2 loads per class plane).
// Per pixel: softmax over 19 classes; accumulate psum[c], inter[c] (predicated
// FFMA keyed on target class), tsum[c] — all in registers.
// ---------------------------------------------------------------------------
__global__ void __launch_bounds__(THREADS, 2)
k_main(const float* __restrict__ pred, const void* __restrict__ tgt) {
    const int n   = blockIdx.x >> 7;          // / BLOCKS_PER_N
    const int blk = blockIdx.x & (BLOCKS_PER_N - 1);
    const int base = blk * PIX_PER_BLOCK;     // pixel index, even-aligned

    const float* __restrict__ p0 = pred + (size_t)n * NCLS * HW;
    const longlong2* __restrict__ t64p =
        (const longlong2*)((const long long*)tgt + (size_t)n * HW);
    const int2* __restrict__ t32p =
        (const int2*)((const int*)tgt + (size_t)n * HW);
    const int is64 = g_t64;

    __shared__ float sI[NCLS];
    __shared__ float sP[NCLS];
    __shared__ int   sT[NCLS];
    if (threadIdx.x < NCLS) {
        sI[threadIdx.x] = 0.0f;
        sP[threadIdx.x] = 0.0f;
        sT[threadIdx.x] = 0;
    }

    float aI[NCLS], aP[NCLS];
    int   aT[NCLS];
    #pragma unroll
    for (int c = 0; c < NCLS; c++) { aI[c] = 0.0f; aP[c] = 0.0f; aT[c] = 0; }

    #pragma unroll
    for (int it = 0; it < ITERS; it++) {
        const int pp = (base >> 1) + it * THREADS + threadIdx.x; // pixel-pair idx

        // target pair load first (overlaps with class-plane loads)
        int t0, t1;
        if (is64) {
            longlong2 tt = __ldcs(t64p + pp);
            t0 = (int)tt.x; t1 = (int)tt.y;
        } else {
            int2 tt = __ldcs(t32p + pp);
            t0 = tt.x; t1 = tt.y;
        }

        // 19 independent coalesced 8B streaming loads -> high MLP
        float2 e[NCLS];
        #pragma unroll
        for (int c = 0; c < NCLS; c++)
            e[c] = __ldcs((const float2*)(p0 + (size_t)c * HW) + pp);

        float m0 = e[0].x, m1 = e[0].y;
        #pragma unroll
        for (int c = 1; c < NCLS; c++) {
            m0 = fmaxf(m0, e[c].x);
            m1 = fmaxf(m1, e[c].y);
        }

        float s0 = 0.0f, s1 = 0.0f;
        #pragma unroll
        for (int c = 0; c < NCLS; c++) {
            e[c].x = __expf(e[c].x - m0); s0 += e[c].x;
            e[c].y = __expf(e[c].y - m1); s1 += e[c].y;
        }
        const float inv0 = __fdividef(1.0f, s0);
        const float inv1 = __fdividef(1.0f, s1);

        #pragma unroll
        for (int c = 0; c < NCLS; c++) {
            aP[c] = fmaf(e[c].x, inv0, aP[c]);
            aP[c] = fmaf(e[c].y, inv1, aP[c]);
            const float sel0 = (t0 == c) ? inv0 : 0.0f;  // no dynamic reg index
            const float sel1 = (t1 == c) ? inv1 : 0.0f;
            aI[c] = fmaf(e[c].x, sel0, aI[c]);
            aI[c] = fmaf(e[c].y, sel1, aI[c]);
            aT[c] += (t0 == c) + (t1 == c);
        }
    }

    // warp butterfly reduce all 57 accumulators
    #pragma unroll
    for (int c = 0; c < NCLS; c++) {
        #pragma unroll
        for (int o = 16; o > 0; o >>= 1) {
            aP[c] += __shfl_xor_sync(0xffffffffu, aP[c], o);
            aI[c] += __shfl_xor_sync(0xffffffffu, aI[c], o);
            aT[c] += __shfl_xor_sync(0xffffffffu, aT[c], o);
        }
    }

    __syncthreads();  // shared init done before atomics
    if ((threadIdx.x & 31) == 0) {
        #pragma unroll
        for (int c = 0; c < NCLS; c++) {
            atomicAdd(&sP[c], aP[c]);
            atomicAdd(&sI[c], aI[c]);
            atomicAdd(&sT[c], aT[c]);
        }
    }
    __syncthreads();

    if (threadIdx.x < NCLS) {
        const int c = threadIdx.x;
        atomicAdd(&g_psum [n * NCLS + c], sP[c]);
        atomicAdd(&g_inter[n * NCLS + c], sI[c]);
        atomicAdd(&g_tsum [n * NCLS + c], (float)sT[c]);
    }
}

// ---------------------------------------------------------------------------
// Kernel 2: final scalar: mean over n of (1 - (2I+1)/(P+T+1)), summed over c, /C
// ---------------------------------------------------------------------------
__global__ void k_final(float* __restrict__ out) {
    const int c = threadIdx.x;
    float v = 0.0f;
    if (c < NCLS) {
        float acc = 0.0f;
        #pragma unroll
        for (int n = 0; n < NBATCH; n++) {
            const float I = g_inter[n * NCLS + c];
            const float P = g_psum [n * NCLS + c];
            const float T = g_tsum [n * NCLS + c];
            acc += 1.0f - (2.0f * I + 1.0f) / (P + T + 1.0f);
        }
        v = acc * (1.0f / (float)NBATCH);
    }
    #pragma unroll
    for (int o = 16; o > 0; o >>= 1) v += __shfl_xor_sync(0xffffffffu, v, o);
    if (c == 0) out[0] = v * (1.0f / (float)NCLS);
}

// ---------------------------------------------------------------------------
extern "C" void kernel_launch(void* const* d_in, const int* in_sizes, int n_in,
                              void* d_out, int out_size) {
    // robust input identification: predict has 8*19*512*512 elems, target 8*512*512
    int ip = 0, it = 1;
    if (n_in >= 2 && in_sizes[1] > in_sizes[0]) { ip = 1; it = 0; }

    const float* pred = (const float*)d_in[ip];
    const void*  tgt  = d_in[it];

    k_init<<<1, 512>>>((const unsigned int*)tgt);
    k_main<<<NBATCH * BLOCKS_PER_N, THREADS>>>(pred, tgt);
    k_final<<<1, 32>>>((float*)d_out);
}